// round 4
// baseline (speedup 1.0000x reference)
#include <cuda_runtime.h>
#include <cuda_bf16.h>

#define NMAX 100000
#define EMAX 1250000
#define DD 64

typedef unsigned long long u64;

__device__ __forceinline__ u64 ffma2(u64 a, u64 b, u64 c) {
    u64 d;
    asm("fma.rn.f32x2 %0, %1, %2, %3;" : "=l"(d) : "l"(a), "l"(b), "l"(c));
    return d;
}
__device__ __forceinline__ u64 pack2(float lo, float hi) {
    u64 d;
    asm("mov.b64 %0, {%1, %2};" : "=l"(d) : "r"(__float_as_uint(lo)), "r"(__float_as_uint(hi)));
    return d;
}
__device__ __forceinline__ float2 unpack2(u64 v) {
    unsigned lo, hi;
    asm("mov.b64 {%0, %1}, %2;" : "=r"(lo), "=r"(hi) : "l"(v));
    return make_float2(__uint_as_float(lo), __uint_as_float(hi));
}

// ---------------- scratch ----------------
__device__ int   g_degi[NMAX];
__device__ float g_dis[NMAX];
__device__ int   g_rowptr[NMAX + 1];
__device__ int   g_cursor[NMAX];
__device__ int   g_csr[EMAX];
__device__ int   g_blocksums[512];
__device__ float g_bufA[(size_t)NMAX * DD];
__device__ float g_bufB[(size_t)NMAX * DD];
__device__ float g_bufC[(size_t)NMAX * DD];

// ---------------- degree / norm ----------------
__global__ void deg_count_kernel(const int* __restrict__ dst, int E, int* __restrict__ degi) {
    int i = blockIdx.x * blockDim.x + threadIdx.x;
    if (i < E) atomicAdd(&degi[dst[i]], 1);
}
__global__ void dis_kernel(const int* __restrict__ degi, float* __restrict__ dis, int n) {
    int i = blockIdx.x * blockDim.x + threadIdx.x;
    if (i < n) dis[i] = rsqrtf((float)degi[i] + 1.0f);
}

// ---------------- exclusive scan (n <= 512*512) ----------------
__global__ void scan1_kernel(const int* __restrict__ cnt, int* __restrict__ out,
                             int* __restrict__ bsums, int n) {
    __shared__ int s[512];
    int i = blockIdx.x * 512 + threadIdx.x;
    int v = (i < n) ? cnt[i] : 0;
    s[threadIdx.x] = v;
    __syncthreads();
    for (int off = 1; off < 512; off <<= 1) {
        int t = (threadIdx.x >= off) ? s[threadIdx.x - off] : 0;
        __syncthreads();
        s[threadIdx.x] += t;
        __syncthreads();
    }
    if (i < n) out[i] = s[threadIdx.x] - v;
    if (threadIdx.x == 511) bsums[blockIdx.x] = s[511];
}
__global__ void scan2_kernel(int* __restrict__ bsums, int nb) {
    __shared__ int s[512];
    int v = (threadIdx.x < nb) ? bsums[threadIdx.x] : 0;
    s[threadIdx.x] = v;
    __syncthreads();
    for (int off = 1; off < 512; off <<= 1) {
        int t = (threadIdx.x >= off) ? s[threadIdx.x - off] : 0;
        __syncthreads();
        s[threadIdx.x] += t;
        __syncthreads();
    }
    if (threadIdx.x < nb) bsums[threadIdx.x] = s[threadIdx.x] - v;
}
__global__ void scan3_kernel(int* __restrict__ rowptr, const int* __restrict__ bsums,
                             int* __restrict__ cursor, int n, int E) {
    int i = blockIdx.x * 512 + threadIdx.x;
    if (i < n) {
        int v = rowptr[i] + bsums[blockIdx.x];
        rowptr[i] = v;
        cursor[i] = v;
    }
    if (i == n) rowptr[n] = E;
}
__global__ void fill_csr_kernel(const int* __restrict__ src, const int* __restrict__ dst,
                                int* __restrict__ cursor, int* __restrict__ csr, int E) {
    int i = blockIdx.x * blockDim.x + threadIdx.x;
    if (i < E) {
        int pos = atomicAdd(&cursor[dst[i]], 1);
        csr[pos] = src[i];
    }
}

// ---------------- gather (CSR), R2-style broadcast loads ----------------
// GCN=true : out = relu?(sum_e xw[s]*dis[s]*dis[d] + xw[d]*dis[d]^2 + bias)
// GCN=false: out = (sum_e h[s]) / max(deg,1)   (mean folded in)
template <bool GCN, bool RELU>
__global__ void gather_kernel(const int* __restrict__ rowptr, const int* __restrict__ csr,
                              const float* __restrict__ xw, const float* __restrict__ dis,
                              const float* __restrict__ bias, float* __restrict__ out, int n) {
    int node = blockIdx.x * 16 + (threadIdx.x >> 4);
    int q = threadIdx.x & 15;
    if (node >= n) return;
    int beg = rowptr[node], end = rowptr[node + 1];
    float4 acc = make_float4(0.f, 0.f, 0.f, 0.f);
    const float4* xwv = (const float4*)xw;
    int e = beg;
    for (; e + 1 < end; e += 2) {
        int s0 = csr[e], s1 = csr[e + 1];
        float4 v0 = xwv[(size_t)s0 * 16 + q];
        float4 v1 = xwv[(size_t)s1 * 16 + q];
        if (GCN) {
            float w0 = dis[s0], w1 = dis[s1];
            acc.x += v0.x * w0 + v1.x * w1;
            acc.y += v0.y * w0 + v1.y * w1;
            acc.z += v0.z * w0 + v1.z * w1;
            acc.w += v0.w * w0 + v1.w * w1;
        } else {
            acc.x += v0.x + v1.x; acc.y += v0.y + v1.y;
            acc.z += v0.z + v1.z; acc.w += v0.w + v1.w;
        }
    }
    if (e < end) {
        int s = csr[e];
        float4 v = xwv[(size_t)s * 16 + q];
        float w = GCN ? dis[s] : 1.0f;
        acc.x += v.x * w; acc.y += v.y * w; acc.z += v.z * w; acc.w += v.w * w;
    }
    if (GCN) {
        float dd = dis[node];
        float d2 = dd * dd;
        float4 xv = xwv[(size_t)node * 16 + q];
        float4 bb = ((const float4*)bias)[q];
        acc.x = fmaf(acc.x, dd, fmaf(xv.x, d2, bb.x));
        acc.y = fmaf(acc.y, dd, fmaf(xv.y, d2, bb.y));
        acc.z = fmaf(acc.z, dd, fmaf(xv.z, d2, bb.z));
        acc.w = fmaf(acc.w, dd, fmaf(xv.w, d2, bb.w));
        if (RELU) {
            acc.x = fmaxf(acc.x, 0.f); acc.y = fmaxf(acc.y, 0.f);
            acc.z = fmaxf(acc.z, 0.f); acc.w = fmaxf(acc.w, 0.f);
        }
    } else {
        float dinv = 1.0f / fmaxf((float)(end - beg), 1.0f);
        acc.x *= dinv; acc.y *= dinv; acc.z *= dinv; acc.w *= dinv;
    }
    ((float4*)out)[(size_t)node * 16 + q] = acc;
}

// ---------------- GEMM via FFMA2, W duplicated in smem ----------------
// Wd[k*64+c] = (W[k][c], W[k][c]); Xs scalar [64][65] (conflict-free both ways).
// Thread: 4 rows x 4 cols. Per k: xp0=(x_r0,x_r1), xp1=(x_r2,x_r3); 8 FFMA2.
// dyn smem: Wd 32768 + Xs 16640 = 49408
template <bool RELU, bool BIAS>
__global__ void __launch_bounds__(256) gemm64_kernel(
    const float* __restrict__ X, const float* __restrict__ W,
    const float* __restrict__ bias, float* __restrict__ out, int n) {
    extern __shared__ char smraw[];
    u64*   Wd = (u64*)smraw;
    float (*Xs)[65] = (float (*)[65])(smraw + 32768);
    int tid = threadIdx.x;
    int row0 = blockIdx.x * 64;

    for (int i = tid; i < 4096; i += 256) {
        float w = W[i];
        Wd[i] = pack2(w, w);            // coalesced u64 store
    }
    for (int j = tid; j < 1024; j += 256) {
        int r = j >> 4, cg = j & 15;
        float4 v = (row0 + r < n) ? ((const float4*)X)[(size_t)(row0 + r) * 16 + cg]
                                  : make_float4(0.f, 0.f, 0.f, 0.f);
        int c = cg * 4;
        Xs[r][c] = v.x; Xs[r][c + 1] = v.y; Xs[r][c + 2] = v.z; Xs[r][c + 3] = v.w;
    }
    __syncthreads();

    int rq = (tid >> 4) * 4;
    int cq = (tid & 15) * 4;
    u64 acc[2][4];
#pragma unroll
    for (int c = 0; c < 4; c++) { acc[0][c] = 0ull; acc[1][c] = 0ull; }

#pragma unroll 4
    for (int k = 0; k < 64; k++) {
        const u64* wr = &Wd[k * 64 + cq];
        u64 w0 = wr[0], w1 = wr[1], w2 = wr[2], w3 = wr[3];
        u64 xp0 = pack2(Xs[rq + 0][k], Xs[rq + 1][k]);
        u64 xp1 = pack2(Xs[rq + 2][k], Xs[rq + 3][k]);
        acc[0][0] = ffma2(xp0, w0, acc[0][0]); acc[0][1] = ffma2(xp0, w1, acc[0][1]);
        acc[0][2] = ffma2(xp0, w2, acc[0][2]); acc[0][3] = ffma2(xp0, w3, acc[0][3]);
        acc[1][0] = ffma2(xp1, w0, acc[1][0]); acc[1][1] = ffma2(xp1, w1, acc[1][1]);
        acc[1][2] = ffma2(xp1, w2, acc[1][2]); acc[1][3] = ffma2(xp1, w3, acc[1][3]);
    }

    int cg = tid & 15;
    float4 bb = BIAS ? ((const float4*)bias)[cg] : make_float4(0.f, 0.f, 0.f, 0.f);
#pragma unroll
    for (int p = 0; p < 2; p++) {
        float2 c0 = unpack2(acc[p][0]), c1 = unpack2(acc[p][1]);
        float2 c2 = unpack2(acc[p][2]), c3 = unpack2(acc[p][3]);
        int rA = row0 + rq + 2 * p;
        if (rA < n) {
            float4 o = make_float4(c0.x + bb.x, c1.x + bb.y, c2.x + bb.z, c3.x + bb.w);
            if (RELU) { o.x = fmaxf(o.x, 0.f); o.y = fmaxf(o.y, 0.f); o.z = fmaxf(o.z, 0.f); o.w = fmaxf(o.w, 0.f); }
            ((float4*)out)[(size_t)rA * 16 + cg] = o;
        }
        if (rA + 1 < n) {
            float4 o = make_float4(c0.y + bb.x, c1.y + bb.y, c2.y + bb.z, c3.y + bb.w);
            if (RELU) { o.x = fmaxf(o.x, 0.f); o.y = fmaxf(o.y, 0.f); o.z = fmaxf(o.z, 0.f); o.w = fmaxf(o.w, 0.f); }
            ((float4*)out)[(size_t)(rA + 1) * 16 + cg] = o;
        }
    }
}

// ---------------- SAGE combine via FFMA2: out = act(M @ Wl + bl + H @ Wr + H) ----------------
// dyn smem: Wld 32768 + Wrd 32768 + Ms 16640 + Hs 16640 = 98816
template <bool RELU>
__global__ void __launch_bounds__(256) sage64_kernel(
    const float* __restrict__ M, const float* __restrict__ H,
    const float* __restrict__ Wl, const float* __restrict__ bl,
    const float* __restrict__ Wr, float* __restrict__ out, int n) {
    extern __shared__ char smraw[];
    u64*   Wld = (u64*)smraw;
    u64*   Wrd = (u64*)(smraw + 32768);
    float (*Ms)[65] = (float (*)[65])(smraw + 65536);
    float (*Hs)[65] = (float (*)[65])(smraw + 65536 + 16640);
    int tid = threadIdx.x;
    int row0 = blockIdx.x * 64;

    for (int i = tid; i < 4096; i += 256) {
        float a = Wl[i], b = Wr[i];
        Wld[i] = pack2(a, a);
        Wrd[i] = pack2(b, b);
    }
    for (int j = tid; j < 1024; j += 256) {
        int r = j >> 4, cg = j & 15;
        float4 m = make_float4(0.f, 0.f, 0.f, 0.f), h = m;
        if (row0 + r < n) {
            m = ((const float4*)M)[(size_t)(row0 + r) * 16 + cg];
            h = ((const float4*)H)[(size_t)(row0 + r) * 16 + cg];
        }
        int c = cg * 4;
        Ms[r][c] = m.x; Ms[r][c + 1] = m.y; Ms[r][c + 2] = m.z; Ms[r][c + 3] = m.w;
        Hs[r][c] = h.x; Hs[r][c + 1] = h.y; Hs[r][c + 2] = h.z; Hs[r][c + 3] = h.w;
    }
    __syncthreads();

    int rq = (tid >> 4) * 4;
    int cq = (tid & 15) * 4;
    u64 acc[2][4];
#pragma unroll
    for (int c = 0; c < 4; c++) { acc[0][c] = 0ull; acc[1][c] = 0ull; }

#pragma unroll 2
    for (int k = 0; k < 64; k++) {
        const u64* wlr = &Wld[k * 64 + cq];
        const u64* wrr = &Wrd[k * 64 + cq];
        u64 mp0 = pack2(Ms[rq + 0][k], Ms[rq + 1][k]);
        u64 mp1 = pack2(Ms[rq + 2][k], Ms[rq + 3][k]);
        u64 hp0 = pack2(Hs[rq + 0][k], Hs[rq + 1][k]);
        u64 hp1 = pack2(Hs[rq + 2][k], Hs[rq + 3][k]);
#pragma unroll
        for (int c = 0; c < 4; c++) {
            acc[0][c] = ffma2(mp0, wlr[c], ffma2(hp0, wrr[c], acc[0][c]));
            acc[1][c] = ffma2(mp1, wlr[c], ffma2(hp1, wrr[c], acc[1][c]));
        }
    }

    int cg = tid & 15;
    float4 bb = ((const float4*)bl)[cg];
    int c0i = cg * 4;
#pragma unroll
    for (int p = 0; p < 2; p++) {
        float2 c0 = unpack2(acc[p][0]), c1 = unpack2(acc[p][1]);
        float2 c2 = unpack2(acc[p][2]), c3 = unpack2(acc[p][3]);
        int rA = row0 + rq + 2 * p;
        if (rA < n) {
            int rl = rq + 2 * p;
            float4 o = make_float4(c0.x + bb.x + Hs[rl][c0i + 0],
                                   c1.x + bb.y + Hs[rl][c0i + 1],
                                   c2.x + bb.z + Hs[rl][c0i + 2],
                                   c3.x + bb.w + Hs[rl][c0i + 3]);
            if (RELU) { o.x = fmaxf(o.x, 0.f); o.y = fmaxf(o.y, 0.f); o.z = fmaxf(o.z, 0.f); o.w = fmaxf(o.w, 0.f); }
            ((float4*)out)[(size_t)rA * 16 + cg] = o;
        }
        if (rA + 1 < n) {
            int rl = rq + 2 * p + 1;
            float4 o = make_float4(c0.y + bb.x + Hs[rl][c0i + 0],
                                   c1.y + bb.y + Hs[rl][c0i + 1],
                                   c2.y + bb.z + Hs[rl][c0i + 2],
                                   c3.y + bb.w + Hs[rl][c0i + 3]);
            if (RELU) { o.x = fmaxf(o.x, 0.f); o.y = fmaxf(o.y, 0.f); o.z = fmaxf(o.z, 0.f); o.w = fmaxf(o.w, 0.f); }
            ((float4*)out)[(size_t)(rA + 1) * 16 + cg] = o;
        }
    }
}

// ---------------- launch ----------------
extern "C" void kernel_launch(void* const* d_in, const int* in_sizes, int n_in,
                              void* d_out, int out_size) {
    const float* x      = (const float*)d_in[0];
    const int*   ei     = (const int*)d_in[1];
    const float* gcn1_w = (const float*)d_in[2];
    const float* gcn1_b = (const float*)d_in[3];
    const float* s1lw   = (const float*)d_in[4];
    const float* s1lb   = (const float*)d_in[5];
    const float* s1rw   = (const float*)d_in[6];
    const float* s2lw   = (const float*)d_in[7];
    const float* s2lb   = (const float*)d_in[8];
    const float* s2rw   = (const float*)d_in[9];
    const float* linw   = (const float*)d_in[10];
    const float* linb   = (const float*)d_in[11];
    const float* gcn2_w = (const float*)d_in[12];
    const float* gcn2_b = (const float*)d_in[13];

    int n = in_sizes[0] / 64;
    int E = in_sizes[1] / 2;
    const int* src = ei;
    const int* dst = ei + E;

    int *degi, *rowptr, *cursor, *csr, *bsums;
    float *dis, *A, *B, *C;
    cudaGetSymbolAddress((void**)&degi, g_degi);
    cudaGetSymbolAddress((void**)&dis, g_dis);
    cudaGetSymbolAddress((void**)&rowptr, g_rowptr);
    cudaGetSymbolAddress((void**)&cursor, g_cursor);
    cudaGetSymbolAddress((void**)&csr, g_csr);
    cudaGetSymbolAddress((void**)&bsums, g_blocksums);
    cudaGetSymbolAddress((void**)&A, g_bufA);
    cudaGetSymbolAddress((void**)&B, g_bufB);
    cudaGetSymbolAddress((void**)&C, g_bufC);

    const int GEMM_SMEM = 49408;
    const int SAGE_SMEM = 98816;
    cudaFuncSetAttribute(gemm64_kernel<false, false>, cudaFuncAttributeMaxDynamicSharedMemorySize, GEMM_SMEM);
    cudaFuncSetAttribute(gemm64_kernel<true, true>,   cudaFuncAttributeMaxDynamicSharedMemorySize, GEMM_SMEM);
    cudaFuncSetAttribute(sage64_kernel<true>,  cudaFuncAttributeMaxDynamicSharedMemorySize, SAGE_SMEM);
    cudaFuncSetAttribute(sage64_kernel<false>, cudaFuncAttributeMaxDynamicSharedMemorySize, SAGE_SMEM);

    const int GEMM_GRID = (n + 63) / 64;
    const int GATH_GRID = (n + 15) / 16;
    const int NB = (n + 511) / 512;

    // degrees + CSR build
    cudaMemsetAsync(degi, 0, n * sizeof(int));
    deg_count_kernel<<<(E + 255) / 256, 256>>>(dst, E, degi);
    dis_kernel<<<(n + 255) / 256, 256>>>(degi, dis, n);
    scan1_kernel<<<NB, 512>>>(degi, rowptr, bsums, n);
    scan2_kernel<<<1, 512>>>(bsums, NB);
    scan3_kernel<<<(n + 512) / 512, 512>>>(rowptr, bsums, cursor, n, E);
    fill_csr_kernel<<<(E + 255) / 256, 256>>>(src, dst, cursor, csr, E);

    // ---- layer 0: GCN1 + relu ----
    gemm64_kernel<false, false><<<GEMM_GRID, 256, GEMM_SMEM>>>(x, gcn1_w, nullptr, A, n);
    gather_kernel<true, true><<<GATH_GRID, 256>>>(rowptr, csr, A, dis, gcn1_b, C, n);

    // ---- layer 1: SAGE1 + residual + relu ----
    gather_kernel<false, false><<<GATH_GRID, 256>>>(rowptr, csr, C, dis, nullptr, B, n);  // mean
    sage64_kernel<true><<<GEMM_GRID, 256, SAGE_SMEM>>>(B, C, s1lw, s1lb, s1rw, A, n);

    // ---- layer 2: SAGE2 + residual ----
    gather_kernel<false, false><<<GATH_GRID, 256>>>(rowptr, csr, A, dis, nullptr, B, n);  // mean
    sage64_kernel<false><<<GEMM_GRID, 256, SAGE_SMEM>>>(B, A, s2lw, s2lb, s2rw, C, n);

    // ---- lin + relu ----
    gemm64_kernel<true, true><<<GEMM_GRID, 256, GEMM_SMEM>>>(C, linw, linb, A, n);

    // ---- layer 3: GCN2 ----
    gemm64_kernel<false, false><<<GEMM_GRID, 256, GEMM_SMEM>>>(A, gcn2_w, nullptr, C, n);
    gather_kernel<true, false><<<GATH_GRID, 256>>>(rowptr, csr, C, dis, gcn2_b, (float*)d_out, n);
}

// round 5
// speedup vs baseline: 2.0695x; 2.0695x over previous
#include <cuda_runtime.h>
#include <cuda_bf16.h>

#define NMAX 100000
#define EMAX 1250000
#define DD 64

// ---------------- scratch ----------------
__device__ int   g_degi[NMAX];
__device__ float g_dis[NMAX];
__device__ int   g_rowptr[NMAX + 1];
__device__ int   g_cursor[NMAX];
__device__ int   g_csr[EMAX];
__device__ int   g_blocksums[512];
__device__ float g_bufA[(size_t)NMAX * DD];
__device__ float g_bufB[(size_t)NMAX * DD];
__device__ float g_bufC[(size_t)NMAX * DD];

// ---------------- tf32 helpers ----------------
__device__ __forceinline__ unsigned f2tf(float f) {
    unsigned u;
    asm("cvt.rna.tf32.f32 %0, %1;" : "=r"(u) : "f"(f));
    return u;
}
__device__ __forceinline__ void mma8(float c[4], unsigned a0, unsigned a1, unsigned a2,
                                     unsigned a3, unsigned b0, unsigned b1) {
    asm("mma.sync.aligned.m16n8k8.row.col.f32.tf32.tf32.f32 "
        "{%0,%1,%2,%3},{%4,%5,%6,%7},{%8,%9},{%0,%1,%2,%3};"
        : "+f"(c[0]), "+f"(c[1]), "+f"(c[2]), "+f"(c[3])
        : "r"(a0), "r"(a1), "r"(a2), "r"(a3), "r"(b0), "r"(b1));
}

// ---------------- degree / norm ----------------
__global__ void deg_count_kernel(const int* __restrict__ dst, int E, int* __restrict__ degi) {
    int i = blockIdx.x * blockDim.x + threadIdx.x;
    if (i < E) atomicAdd(&degi[dst[i]], 1);
}
__global__ void dis_kernel(const int* __restrict__ degi, float* __restrict__ dis, int n) {
    int i = blockIdx.x * blockDim.x + threadIdx.x;
    if (i < n) dis[i] = rsqrtf((float)degi[i] + 1.0f);
}

// ---------------- exclusive scan (n <= 512*512) ----------------
__global__ void scan1_kernel(const int* __restrict__ cnt, int* __restrict__ out,
                             int* __restrict__ bsums, int n) {
    __shared__ int s[512];
    int i = blockIdx.x * 512 + threadIdx.x;
    int v = (i < n) ? cnt[i] : 0;
    s[threadIdx.x] = v;
    __syncthreads();
    for (int off = 1; off < 512; off <<= 1) {
        int t = (threadIdx.x >= off) ? s[threadIdx.x - off] : 0;
        __syncthreads();
        s[threadIdx.x] += t;
        __syncthreads();
    }
    if (i < n) out[i] = s[threadIdx.x] - v;
    if (threadIdx.x == 511) bsums[blockIdx.x] = s[511];
}
__global__ void scan2_kernel(int* __restrict__ bsums, int nb) {
    __shared__ int s[512];
    int v = (threadIdx.x < nb) ? bsums[threadIdx.x] : 0;
    s[threadIdx.x] = v;
    __syncthreads();
    for (int off = 1; off < 512; off <<= 1) {
        int t = (threadIdx.x >= off) ? s[threadIdx.x - off] : 0;
        __syncthreads();
        s[threadIdx.x] += t;
        __syncthreads();
    }
    if (threadIdx.x < nb) bsums[threadIdx.x] = s[threadIdx.x] - v;
}
__global__ void scan3_kernel(int* __restrict__ rowptr, const int* __restrict__ bsums,
                             int* __restrict__ cursor, int n, int E) {
    int i = blockIdx.x * 512 + threadIdx.x;
    if (i < n) {
        int v = rowptr[i] + bsums[blockIdx.x];
        rowptr[i] = v;
        cursor[i] = v;
    }
    if (i == n) rowptr[n] = E;
}
__global__ void fill_csr_kernel(const int* __restrict__ src, const int* __restrict__ dst,
                                int* __restrict__ cursor, int* __restrict__ csr, int E) {
    int i = blockIdx.x * blockDim.x + threadIdx.x;
    if (i < E) {
        int pos = atomicAdd(&cursor[dst[i]], 1);
        csr[pos] = src[i];
    }
}

// ---------------- gather (CSR), R2-proven broadcast loads ----------------
template <bool GCN, bool RELU>
__global__ void gather_kernel(const int* __restrict__ rowptr, const int* __restrict__ csr,
                              const float* __restrict__ xw, const float* __restrict__ dis,
                              const float* __restrict__ bias, float* __restrict__ out, int n) {
    int node = blockIdx.x * 16 + (threadIdx.x >> 4);
    int q = threadIdx.x & 15;
    if (node >= n) return;
    int beg = rowptr[node], end = rowptr[node + 1];
    float4 acc = make_float4(0.f, 0.f, 0.f, 0.f);
    const float4* xwv = (const float4*)xw;
    int e = beg;
    for (; e + 1 < end; e += 2) {
        int s0 = csr[e], s1 = csr[e + 1];
        float4 v0 = xwv[(size_t)s0 * 16 + q];
        float4 v1 = xwv[(size_t)s1 * 16 + q];
        if (GCN) {
            float w0 = dis[s0], w1 = dis[s1];
            acc.x += v0.x * w0 + v1.x * w1;
            acc.y += v0.y * w0 + v1.y * w1;
            acc.z += v0.z * w0 + v1.z * w1;
            acc.w += v0.w * w0 + v1.w * w1;
        } else {
            acc.x += v0.x + v1.x; acc.y += v0.y + v1.y;
            acc.z += v0.z + v1.z; acc.w += v0.w + v1.w;
        }
    }
    if (e < end) {
        int s = csr[e];
        float4 v = xwv[(size_t)s * 16 + q];
        float w = GCN ? dis[s] : 1.0f;
        acc.x += v.x * w; acc.y += v.y * w; acc.z += v.z * w; acc.w += v.w * w;
    }
    if (GCN) {
        float dd = dis[node];
        float d2 = dd * dd;
        float4 xv = xwv[(size_t)node * 16 + q];
        float4 bb = ((const float4*)bias)[q];
        acc.x = fmaf(acc.x, dd, fmaf(xv.x, d2, bb.x));
        acc.y = fmaf(acc.y, dd, fmaf(xv.y, d2, bb.y));
        acc.z = fmaf(acc.z, dd, fmaf(xv.z, d2, bb.z));
        acc.w = fmaf(acc.w, dd, fmaf(xv.w, d2, bb.w));
        if (RELU) {
            acc.x = fmaxf(acc.x, 0.f); acc.y = fmaxf(acc.y, 0.f);
            acc.z = fmaxf(acc.z, 0.f); acc.w = fmaxf(acc.w, 0.f);
        }
    } else {
        float dinv = 1.0f / fmaxf((float)(end - beg), 1.0f);
        acc.x *= dinv; acc.y *= dinv; acc.z *= dinv; acc.w *= dinv;
    }
    ((float4*)out)[(size_t)node * 16 + q] = acc;
}

// ---------------- tensor-core GEMM: out = act(X @ W [+ b]) ----------------
// 256 threads = 8 warps; block covers 128 rows; warp: 16 rows x 64 cols.
// smem: Ws[64][72] tf32 (18432B) + Xs[128][68] fp32 (34816B) = 53248B (dynamic)
#define XS_STRIDE 68
#define WS_STRIDE 72
template <bool RELU, bool BIAS>
__global__ void __launch_bounds__(256) gemm_tc_kernel(
    const float* __restrict__ X, const float* __restrict__ W,
    const float* __restrict__ bias, float* __restrict__ out, int n) {
    extern __shared__ char smraw[];
    float* Ws = (float*)smraw;                       // [64][72], tf32-rounded
    float* Xs = (float*)(smraw + 64 * WS_STRIDE * 4);  // [128][68], fp32
    int tid = threadIdx.x;
    int row0 = blockIdx.x * 128;

    for (int i = tid; i < 4096; i += 256) {
        int k = i >> 6, c = i & 63;
        Ws[k * WS_STRIDE + c] = __uint_as_float(f2tf(W[i]));
    }
    for (int j = tid; j < 2048; j += 256) {
        int r = j >> 4, cg = j & 15;
        float4 v = (row0 + r < n) ? ((const float4*)X)[(size_t)(row0 + r) * 16 + cg]
                                  : make_float4(0.f, 0.f, 0.f, 0.f);
        float* p = &Xs[r * XS_STRIDE + cg * 4];
        p[0] = v.x; p[1] = v.y; p[2] = v.z; p[3] = v.w;
    }
    __syncthreads();

    int warp = tid >> 5;
    int lane = tid & 31;
    int gid = lane >> 2;       // 0..7
    int tig = lane & 3;        // 0..3
    int rlo = warp * 16 + gid; // smem row (lo), rhi = +8

    float c[8][4];
#pragma unroll
    for (int t = 0; t < 8; t++)
#pragma unroll
        for (int j = 0; j < 4; j++) c[t][j] = 0.f;

#pragma unroll
    for (int ks = 0; ks < 8; ks++) {
        int k0 = ks * 8;
        unsigned a0 = f2tf(Xs[rlo * XS_STRIDE + k0 + tig]);
        unsigned a1 = f2tf(Xs[(rlo + 8) * XS_STRIDE + k0 + tig]);
        unsigned a2 = f2tf(Xs[rlo * XS_STRIDE + k0 + tig + 4]);
        unsigned a3 = f2tf(Xs[(rlo + 8) * XS_STRIDE + k0 + tig + 4]);
#pragma unroll
        for (int t = 0; t < 8; t++) {
            int col = t * 8 + gid;
            unsigned b0 = __float_as_uint(Ws[(k0 + tig) * WS_STRIDE + col]);
            unsigned b1 = __float_as_uint(Ws[(k0 + tig + 4) * WS_STRIDE + col]);
            mma8(c[t], a0, a1, a2, a3, b0, b1);
        }
    }

#pragma unroll
    for (int t = 0; t < 8; t++) {
        int colp = t * 4 + tig;            // float2 index: col = 2*colp
        float2 bb = BIAS ? ((const float2*)bias)[colp] : make_float2(0.f, 0.f);
        int row_lo = row0 + warp * 16 + gid;
        int row_hi = row_lo + 8;
        if (row_lo < n) {
            float2 o = make_float2(c[t][0] + bb.x, c[t][1] + bb.y);
            if (RELU) { o.x = fmaxf(o.x, 0.f); o.y = fmaxf(o.y, 0.f); }
            ((float2*)out)[(size_t)row_lo * 32 + colp] = o;
        }
        if (row_hi < n) {
            float2 o = make_float2(c[t][2] + bb.x, c[t][3] + bb.y);
            if (RELU) { o.x = fmaxf(o.x, 0.f); o.y = fmaxf(o.y, 0.f); }
            ((float2*)out)[(size_t)row_hi * 32 + colp] = o;
        }
    }
}

// ---------------- tensor-core SAGE: out = act(M @ Wl + bl + H @ Wr + H) ----------------
// smem: Wcat[128][72] tf32 (36864B) + Ms[128][68] (34816B) + Hs[128][68] (34816B) = 106496B
template <bool RELU>
__global__ void __launch_bounds__(256) sage_tc_kernel(
    const float* __restrict__ M, const float* __restrict__ H,
    const float* __restrict__ Wl, const float* __restrict__ bl,
    const float* __restrict__ Wr, float* __restrict__ out, int n) {
    extern __shared__ char smraw[];
    float* Wc = (float*)smraw;                             // [128][72], k<64: Wl, k>=64: Wr
    float* Ms = (float*)(smraw + 128 * WS_STRIDE * 4);     // [128][68]
    float* Hs = (float*)(smraw + 128 * WS_STRIDE * 4 + 128 * XS_STRIDE * 4);
    int tid = threadIdx.x;
    int row0 = blockIdx.x * 128;

    for (int i = tid; i < 4096; i += 256) {
        int k = i >> 6, cc = i & 63;
        Wc[k * WS_STRIDE + cc]        = __uint_as_float(f2tf(Wl[i]));
        Wc[(k + 64) * WS_STRIDE + cc] = __uint_as_float(f2tf(Wr[i]));
    }
    for (int j = tid; j < 2048; j += 256) {
        int r = j >> 4, cg = j & 15;
        float4 m = make_float4(0.f, 0.f, 0.f, 0.f), h = m;
        if (row0 + r < n) {
            m = ((const float4*)M)[(size_t)(row0 + r) * 16 + cg];
            h = ((const float4*)H)[(size_t)(row0 + r) * 16 + cg];
        }
        float* pm = &Ms[r * XS_STRIDE + cg * 4];
        float* ph = &Hs[r * XS_STRIDE + cg * 4];
        pm[0] = m.x; pm[1] = m.y; pm[2] = m.z; pm[3] = m.w;
        ph[0] = h.x; ph[1] = h.y; ph[2] = h.z; ph[3] = h.w;
    }
    __syncthreads();

    int warp = tid >> 5;
    int lane = tid & 31;
    int gid = lane >> 2;
    int tig = lane & 3;
    int rlo = warp * 16 + gid;

    float c[8][4];
#pragma unroll
    for (int t = 0; t < 8; t++)
#pragma unroll
        for (int j = 0; j < 4; j++) c[t][j] = 0.f;

#pragma unroll
    for (int ks = 0; ks < 16; ks++) {
        const float* A = (ks < 8) ? Ms : Hs;
        int k0 = (ks & 7) * 8;
        int kw = ks * 8;
        unsigned a0 = f2tf(A[rlo * XS_STRIDE + k0 + tig]);
        unsigned a1 = f2tf(A[(rlo + 8) * XS_STRIDE + k0 + tig]);
        unsigned a2 = f2tf(A[rlo * XS_STRIDE + k0 + tig + 4]);
        unsigned a3 = f2tf(A[(rlo + 8) * XS_STRIDE + k0 + tig + 4]);
#pragma unroll
        for (int t = 0; t < 8; t++) {
            int col = t * 8 + gid;
            unsigned b0 = __float_as_uint(Wc[(kw + tig) * WS_STRIDE + col]);
            unsigned b1 = __float_as_uint(Wc[(kw + tig + 4) * WS_STRIDE + col]);
            mma8(c[t], a0, a1, a2, a3, b0, b1);
        }
    }

#pragma unroll
    for (int t = 0; t < 8; t++) {
        int colp = t * 4 + tig;          // col = 2*colp
        int col = colp * 2;
        float2 bb = ((const float2*)bl)[colp];
        int rl = warp * 16 + gid;
        int row_lo = row0 + rl;
        int row_hi = row_lo + 8;
        if (row_lo < n) {
            float2 o = make_float2(c[t][0] + bb.x + Hs[rl * XS_STRIDE + col],
                                   c[t][1] + bb.y + Hs[rl * XS_STRIDE + col + 1]);
            if (RELU) { o.x = fmaxf(o.x, 0.f); o.y = fmaxf(o.y, 0.f); }
            ((float2*)out)[(size_t)row_lo * 32 + colp] = o;
        }
        if (row_hi < n) {
            float2 o = make_float2(c[t][2] + bb.x + Hs[(rl + 8) * XS_STRIDE + col],
                                   c[t][3] + bb.y + Hs[(rl + 8) * XS_STRIDE + col + 1]);
            if (RELU) { o.x = fmaxf(o.x, 0.f); o.y = fmaxf(o.y, 0.f); }
            ((float2*)out)[(size_t)row_hi * 32 + colp] = o;
        }
    }
}

// ---------------- launch ----------------
extern "C" void kernel_launch(void* const* d_in, const int* in_sizes, int n_in,
                              void* d_out, int out_size) {
    const float* x      = (const float*)d_in[0];
    const int*   ei     = (const int*)d_in[1];
    const float* gcn1_w = (const float*)d_in[2];
    const float* gcn1_b = (const float*)d_in[3];
    const float* s1lw   = (const float*)d_in[4];
    const float* s1lb   = (const float*)d_in[5];
    const float* s1rw   = (const float*)d_in[6];
    const float* s2lw   = (const float*)d_in[7];
    const float* s2lb   = (const float*)d_in[8];
    const float* s2rw   = (const float*)d_in[9];
    const float* linw   = (const float*)d_in[10];
    const float* linb   = (const float*)d_in[11];
    const float* gcn2_w = (const float*)d_in[12];
    const float* gcn2_b = (const float*)d_in[13];

    int n = in_sizes[0] / 64;
    int E = in_sizes[1] / 2;
    const int* src = ei;
    const int* dst = ei + E;

    int *degi, *rowptr, *cursor, *csr, *bsums;
    float *dis, *A, *B, *C;
    cudaGetSymbolAddress((void**)&degi, g_degi);
    cudaGetSymbolAddress((void**)&dis, g_dis);
    cudaGetSymbolAddress((void**)&rowptr, g_rowptr);
    cudaGetSymbolAddress((void**)&cursor, g_cursor);
    cudaGetSymbolAddress((void**)&csr, g_csr);
    cudaGetSymbolAddress((void**)&bsums, g_blocksums);
    cudaGetSymbolAddress((void**)&A, g_bufA);
    cudaGetSymbolAddress((void**)&B, g_bufB);
    cudaGetSymbolAddress((void**)&C, g_bufC);

    const int GEMM_SMEM = 64 * WS_STRIDE * 4 + 128 * XS_STRIDE * 4;          // 53248
    const int SAGE_SMEM = 128 * WS_STRIDE * 4 + 2 * 128 * XS_STRIDE * 4;     // 106496
    cudaFuncSetAttribute(gemm_tc_kernel<false, false>, cudaFuncAttributeMaxDynamicSharedMemorySize, GEMM_SMEM);
    cudaFuncSetAttribute(gemm_tc_kernel<true, true>,   cudaFuncAttributeMaxDynamicSharedMemorySize, GEMM_SMEM);
    cudaFuncSetAttribute(sage_tc_kernel<true>,  cudaFuncAttributeMaxDynamicSharedMemorySize, SAGE_SMEM);
    cudaFuncSetAttribute(sage_tc_kernel<false>, cudaFuncAttributeMaxDynamicSharedMemorySize, SAGE_SMEM);

    const int GEMM_GRID = (n + 127) / 128;
    const int GATH_GRID = (n + 15) / 16;
    const int NB = (n + 511) / 512;

    // degrees + CSR build
    cudaMemsetAsync(degi, 0, n * sizeof(int));
    deg_count_kernel<<<(E + 255) / 256, 256>>>(dst, E, degi);
    dis_kernel<<<(n + 255) / 256, 256>>>(degi, dis, n);
    scan1_kernel<<<NB, 512>>>(degi, rowptr, bsums, n);
    scan2_kernel<<<1, 512>>>(bsums, NB);
    scan3_kernel<<<(n + 512) / 512, 512>>>(rowptr, bsums, cursor, n, E);
    fill_csr_kernel<<<(E + 255) / 256, 256>>>(src, dst, cursor, csr, E);

    // ---- layer 0: GCN1 + relu ----
    gemm_tc_kernel<false, false><<<GEMM_GRID, 256, GEMM_SMEM>>>(x, gcn1_w, nullptr, A, n);
    gather_kernel<true, true><<<GATH_GRID, 256>>>(rowptr, csr, A, dis, gcn1_b, C, n);

    // ---- layer 1: SAGE1 + residual + relu ----
    gather_kernel<false, false><<<GATH_GRID, 256>>>(rowptr, csr, C, dis, nullptr, B, n);  // mean
    sage_tc_kernel<true><<<GEMM_GRID, 256, SAGE_SMEM>>>(B, C, s1lw, s1lb, s1rw, A, n);

    // ---- layer 2: SAGE2 + residual ----
    gather_kernel<false, false><<<GATH_GRID, 256>>>(rowptr, csr, A, dis, nullptr, B, n);  // mean
    sage_tc_kernel<false><<<GEMM_GRID, 256, SAGE_SMEM>>>(B, A, s2lw, s2lb, s2rw, C, n);

    // ---- lin + relu ----
    gemm_tc_kernel<true, true><<<GEMM_GRID, 256, GEMM_SMEM>>>(C, linw, linb, A, n);

    // ---- layer 3: GCN2 ----
    gemm_tc_kernel<false, false><<<GEMM_GRID, 256, GEMM_SMEM>>>(A, gcn2_w, nullptr, C, n);
    gather_kernel<true, false><<<GATH_GRID, 256>>>(rowptr, csr, C, dis, gcn2_b, (float*)d_out, n);
}

// round 6
// speedup vs baseline: 2.1680x; 1.0476x over previous
#include <cuda_runtime.h>
#include <cuda_bf16.h>

#define NMAX 100000
#define EMAX 1250000
#define DD 64

// ---------------- scratch ----------------
__device__ int   g_degi[NMAX];
__device__ float g_dis[NMAX];
__device__ int   g_rowptr[NMAX + 1];
__device__ int   g_cursor[NMAX];
__device__ int   g_csr[EMAX];
__device__ int   g_blocksums[512];
__device__ float g_bufA[(size_t)NMAX * DD];
__device__ float g_bufB[(size_t)NMAX * DD];
__device__ float g_bufC[(size_t)NMAX * DD];

// ---------------- tf32 helpers ----------------
__device__ __forceinline__ unsigned f2tf(float f) {
    unsigned u;
    asm("cvt.rna.tf32.f32 %0, %1;" : "=r"(u) : "f"(f));
    return u;
}
__device__ __forceinline__ void mma8(float c[4], unsigned a0, unsigned a1, unsigned a2,
                                     unsigned a3, unsigned b0, unsigned b1) {
    asm("mma.sync.aligned.m16n8k8.row.col.f32.tf32.tf32.f32 "
        "{%0,%1,%2,%3},{%4,%5,%6,%7},{%8,%9},{%0,%1,%2,%3};"
        : "+f"(c[0]), "+f"(c[1]), "+f"(c[2]), "+f"(c[3])
        : "r"(a0), "r"(a1), "r"(a2), "r"(a3), "r"(b0), "r"(b1));
}

// ---------------- degree ----------------
__global__ void deg_count_kernel(const int* __restrict__ dst, int E, int* __restrict__ degi) {
    int i = blockIdx.x * blockDim.x + threadIdx.x;
    if (i < E) atomicAdd(&degi[dst[i]], 1);
}

// ---------------- exclusive scan (n <= 512*512), fused dis ----------------
__global__ void scan1_kernel(const int* __restrict__ cnt, int* __restrict__ out,
                             int* __restrict__ bsums, float* __restrict__ dis, int n) {
    __shared__ int s[512];
    int i = blockIdx.x * 512 + threadIdx.x;
    int v = (i < n) ? cnt[i] : 0;
    if (i < n) dis[i] = rsqrtf((float)v + 1.0f);
    s[threadIdx.x] = v;
    __syncthreads();
    for (int off = 1; off < 512; off <<= 1) {
        int t = (threadIdx.x >= off) ? s[threadIdx.x - off] : 0;
        __syncthreads();
        s[threadIdx.x] += t;
        __syncthreads();
    }
    if (i < n) out[i] = s[threadIdx.x] - v;
    if (threadIdx.x == 511) bsums[blockIdx.x] = s[511];
}
__global__ void scan2_kernel(int* __restrict__ bsums, int nb) {
    __shared__ int s[512];
    int v = (threadIdx.x < nb) ? bsums[threadIdx.x] : 0;
    s[threadIdx.x] = v;
    __syncthreads();
    for (int off = 1; off < 512; off <<= 1) {
        int t = (threadIdx.x >= off) ? s[threadIdx.x - off] : 0;
        __syncthreads();
        s[threadIdx.x] += t;
        __syncthreads();
    }
    if (threadIdx.x < nb) bsums[threadIdx.x] = s[threadIdx.x] - v;
}
__global__ void scan3_kernel(int* __restrict__ rowptr, const int* __restrict__ bsums,
                             int* __restrict__ cursor, int n, int E) {
    int i = blockIdx.x * 512 + threadIdx.x;
    if (i < n) {
        int v = rowptr[i] + bsums[blockIdx.x];
        rowptr[i] = v;
        cursor[i] = v;
    }
    if (i == n) rowptr[n] = E;
}
__global__ void fill_csr_kernel(const int* __restrict__ src, const int* __restrict__ dst,
                                int* __restrict__ cursor, int* __restrict__ csr, int E) {
    int i = blockIdx.x * blockDim.x + threadIdx.x;
    if (i < E) {
        int pos = atomicAdd(&cursor[dst[i]], 1);
        csr[pos] = src[i];
    }
}

// ---------------- gather (CSR), unroll-4 for MLP ----------------
template <bool GCN, bool RELU>
__global__ void gather_kernel(const int* __restrict__ rowptr, const int* __restrict__ csr,
                              const float* __restrict__ xw, const float* __restrict__ dis,
                              const float* __restrict__ bias, float* __restrict__ out, int n) {
    int node = blockIdx.x * 16 + (threadIdx.x >> 4);
    int q = threadIdx.x & 15;
    if (node >= n) return;
    int beg = rowptr[node], end = rowptr[node + 1];
    float4 acc = make_float4(0.f, 0.f, 0.f, 0.f);
    const float4* __restrict__ xwv = (const float4*)xw;
    int e = beg;
    for (; e + 3 < end; e += 4) {
        int s0 = csr[e], s1 = csr[e + 1], s2 = csr[e + 2], s3 = csr[e + 3];
        float4 v0 = xwv[s0 * 16 + q];
        float4 v1 = xwv[s1 * 16 + q];
        float4 v2 = xwv[s2 * 16 + q];
        float4 v3 = xwv[s3 * 16 + q];
        if (GCN) {
            float w0 = dis[s0], w1 = dis[s1], w2 = dis[s2], w3 = dis[s3];
            acc.x += v0.x * w0 + v1.x * w1 + v2.x * w2 + v3.x * w3;
            acc.y += v0.y * w0 + v1.y * w1 + v2.y * w2 + v3.y * w3;
            acc.z += v0.z * w0 + v1.z * w1 + v2.z * w2 + v3.z * w3;
            acc.w += v0.w * w0 + v1.w * w1 + v2.w * w2 + v3.w * w3;
        } else {
            acc.x += (v0.x + v1.x) + (v2.x + v3.x);
            acc.y += (v0.y + v1.y) + (v2.y + v3.y);
            acc.z += (v0.z + v1.z) + (v2.z + v3.z);
            acc.w += (v0.w + v1.w) + (v2.w + v3.w);
        }
    }
    for (; e < end; e++) {
        int s = csr[e];
        float4 v = xwv[s * 16 + q];
        float w = GCN ? dis[s] : 1.0f;
        acc.x += v.x * w; acc.y += v.y * w; acc.z += v.z * w; acc.w += v.w * w;
    }
    if (GCN) {
        float dd = dis[node];
        float d2 = dd * dd;
        float4 xv = xwv[node * 16 + q];
        float4 bb = ((const float4*)bias)[q];
        acc.x = fmaf(acc.x, dd, fmaf(xv.x, d2, bb.x));
        acc.y = fmaf(acc.y, dd, fmaf(xv.y, d2, bb.y));
        acc.z = fmaf(acc.z, dd, fmaf(xv.z, d2, bb.z));
        acc.w = fmaf(acc.w, dd, fmaf(xv.w, d2, bb.w));
        if (RELU) {
            acc.x = fmaxf(acc.x, 0.f); acc.y = fmaxf(acc.y, 0.f);
            acc.z = fmaxf(acc.z, 0.f); acc.w = fmaxf(acc.w, 0.f);
        }
    } else {
        float dinv = 1.0f / fmaxf((float)(end - beg), 1.0f);
        acc.x *= dinv; acc.y *= dinv; acc.z *= dinv; acc.w *= dinv;
    }
    ((float4*)out)[node * 16 + q] = acc;
}

// ---------------- tensor-core GEMM: out = act(X @ W [+ b]) ----------------
#define XS_STRIDE 68
#define WS_STRIDE 72
template <bool RELU, bool BIAS>
__global__ void __launch_bounds__(256) gemm_tc_kernel(
    const float* __restrict__ X, const float* __restrict__ W,
    const float* __restrict__ bias, float* __restrict__ out, int n) {
    extern __shared__ char smraw[];
    float* Ws = (float*)smraw;                         // [64][72], tf32-rounded
    float* Xs = (float*)(smraw + 64 * WS_STRIDE * 4);  // [128][68], fp32
    int tid = threadIdx.x;
    int row0 = blockIdx.x * 128;

    for (int i = tid; i < 4096; i += 256) {
        int k = i >> 6, c = i & 63;
        Ws[k * WS_STRIDE + c] = __uint_as_float(f2tf(W[i]));
    }
    for (int j = tid; j < 2048; j += 256) {
        int r = j >> 4, cg = j & 15;
        float4 v = (row0 + r < n) ? ((const float4*)X)[(size_t)(row0 + r) * 16 + cg]
                                  : make_float4(0.f, 0.f, 0.f, 0.f);
        float* p = &Xs[r * XS_STRIDE + cg * 4];
        p[0] = v.x; p[1] = v.y; p[2] = v.z; p[3] = v.w;
    }
    __syncthreads();

    int warp = tid >> 5;
    int lane = tid & 31;
    int gid = lane >> 2;
    int tig = lane & 3;
    int rlo = warp * 16 + gid;

    float c[8][4];
#pragma unroll
    for (int t = 0; t < 8; t++)
#pragma unroll
        for (int j = 0; j < 4; j++) c[t][j] = 0.f;

#pragma unroll
    for (int ks = 0; ks < 8; ks++) {
        int k0 = ks * 8;
        unsigned a0 = f2tf(Xs[rlo * XS_STRIDE + k0 + tig]);
        unsigned a1 = f2tf(Xs[(rlo + 8) * XS_STRIDE + k0 + tig]);
        unsigned a2 = f2tf(Xs[rlo * XS_STRIDE + k0 + tig + 4]);
        unsigned a3 = f2tf(Xs[(rlo + 8) * XS_STRIDE + k0 + tig + 4]);
#pragma unroll
        for (int t = 0; t < 8; t++) {
            int col = t * 8 + gid;
            unsigned b0 = __float_as_uint(Ws[(k0 + tig) * WS_STRIDE + col]);
            unsigned b1 = __float_as_uint(Ws[(k0 + tig + 4) * WS_STRIDE + col]);
            mma8(c[t], a0, a1, a2, a3, b0, b1);
        }
    }

#pragma unroll
    for (int t = 0; t < 8; t++) {
        int colp = t * 4 + tig;
        float2 bb = BIAS ? ((const float2*)bias)[colp] : make_float2(0.f, 0.f);
        int row_lo = row0 + warp * 16 + gid;
        int row_hi = row_lo + 8;
        if (row_lo < n) {
            float2 o = make_float2(c[t][0] + bb.x, c[t][1] + bb.y);
            if (RELU) { o.x = fmaxf(o.x, 0.f); o.y = fmaxf(o.y, 0.f); }
            ((float2*)out)[(size_t)row_lo * 32 + colp] = o;
        }
        if (row_hi < n) {
            float2 o = make_float2(c[t][2] + bb.x, c[t][3] + bb.y);
            if (RELU) { o.x = fmaxf(o.x, 0.f); o.y = fmaxf(o.y, 0.f); }
            ((float2*)out)[(size_t)row_hi * 32 + colp] = o;
        }
    }
}

// ---------------- tensor-core SAGE: out = act(M @ Wl + bl + H @ Wr + H) ----------------
template <bool RELU>
__global__ void __launch_bounds__(256) sage_tc_kernel(
    const float* __restrict__ M, const float* __restrict__ H,
    const float* __restrict__ Wl, const float* __restrict__ bl,
    const float* __restrict__ Wr, float* __restrict__ out, int n) {
    extern __shared__ char smraw[];
    float* Wc = (float*)smraw;                          // [128][72]
    float* Ms = (float*)(smraw + 128 * WS_STRIDE * 4);
    float* Hs = (float*)(smraw + 128 * WS_STRIDE * 4 + 128 * XS_STRIDE * 4);
    int tid = threadIdx.x;
    int row0 = blockIdx.x * 128;

    for (int i = tid; i < 4096; i += 256) {
        int k = i >> 6, cc = i & 63;
        Wc[k * WS_STRIDE + cc]        = __uint_as_float(f2tf(Wl[i]));
        Wc[(k + 64) * WS_STRIDE + cc] = __uint_as_float(f2tf(Wr[i]));
    }
    for (int j = tid; j < 2048; j += 256) {
        int r = j >> 4, cg = j & 15;
        float4 m = make_float4(0.f, 0.f, 0.f, 0.f), h = m;
        if (row0 + r < n) {
            m = ((const float4*)M)[(size_t)(row0 + r) * 16 + cg];
            h = ((const float4*)H)[(size_t)(row0 + r) * 16 + cg];
        }
        float* pm = &Ms[r * XS_STRIDE + cg * 4];
        float* ph = &Hs[r * XS_STRIDE + cg * 4];
        pm[0] = m.x; pm[1] = m.y; pm[2] = m.z; pm[3] = m.w;
        ph[0] = h.x; ph[1] = h.y; ph[2] = h.z; ph[3] = h.w;
    }
    __syncthreads();

    int warp = tid >> 5;
    int lane = tid & 31;
    int gid = lane >> 2;
    int tig = lane & 3;
    int rlo = warp * 16 + gid;

    float c[8][4];
#pragma unroll
    for (int t = 0; t < 8; t++)
#pragma unroll
        for (int j = 0; j < 4; j++) c[t][j] = 0.f;

#pragma unroll
    for (int ks = 0; ks < 16; ks++) {
        const float* A = (ks < 8) ? Ms : Hs;
        int k0 = (ks & 7) * 8;
        int kw = ks * 8;
        unsigned a0 = f2tf(A[rlo * XS_STRIDE + k0 + tig]);
        unsigned a1 = f2tf(A[(rlo + 8) * XS_STRIDE + k0 + tig]);
        unsigned a2 = f2tf(A[rlo * XS_STRIDE + k0 + tig + 4]);
        unsigned a3 = f2tf(A[(rlo + 8) * XS_STRIDE + k0 + tig + 4]);
#pragma unroll
        for (int t = 0; t < 8; t++) {
            int col = t * 8 + gid;
            unsigned b0 = __float_as_uint(Wc[(kw + tig) * WS_STRIDE + col]);
            unsigned b1 = __float_as_uint(Wc[(kw + tig + 4) * WS_STRIDE + col]);
            mma8(c[t], a0, a1, a2, a3, b0, b1);
        }
    }

#pragma unroll
    for (int t = 0; t < 8; t++) {
        int colp = t * 4 + tig;
        int col = colp * 2;
        float2 bb = ((const float2*)bl)[colp];
        int rl = warp * 16 + gid;
        int row_lo = row0 + rl;
        int row_hi = row_lo + 8;
        if (row_lo < n) {
            float2 o = make_float2(c[t][0] + bb.x + Hs[rl * XS_STRIDE + col],
                                   c[t][1] + bb.y + Hs[rl * XS_STRIDE + col + 1]);
            if (RELU) { o.x = fmaxf(o.x, 0.f); o.y = fmaxf(o.y, 0.f); }
            ((float2*)out)[(size_t)row_lo * 32 + colp] = o;
        }
        if (row_hi < n) {
            float2 o = make_float2(c[t][2] + bb.x + Hs[(rl + 8) * XS_STRIDE + col],
                                   c[t][3] + bb.y + Hs[(rl + 8) * XS_STRIDE + col + 1]);
            if (RELU) { o.x = fmaxf(o.x, 0.f); o.y = fmaxf(o.y, 0.f); }
            ((float2*)out)[(size_t)row_hi * 32 + colp] = o;
        }
    }
}

// ---------------- launch ----------------
extern "C" void kernel_launch(void* const* d_in, const int* in_sizes, int n_in,
                              void* d_out, int out_size) {
    const float* x      = (const float*)d_in[0];
    const int*   ei     = (const int*)d_in[1];
    const float* gcn1_w = (const float*)d_in[2];
    const float* gcn1_b = (const float*)d_in[3];
    const float* s1lw   = (const float*)d_in[4];
    const float* s1lb   = (const float*)d_in[5];
    const float* s1rw   = (const float*)d_in[6];
    const float* s2lw   = (const float*)d_in[7];
    const float* s2lb   = (const float*)d_in[8];
    const float* s2rw   = (const float*)d_in[9];
    const float* linw   = (const float*)d_in[10];
    const float* linb   = (const float*)d_in[11];
    const float* gcn2_w = (const float*)d_in[12];
    const float* gcn2_b = (const float*)d_in[13];

    int n = in_sizes[0] / 64;
    int E = in_sizes[1] / 2;
    const int* src = ei;
    const int* dst = ei + E;

    int *degi, *rowptr, *cursor, *csr, *bsums;
    float *dis, *A, *B, *C;
    cudaGetSymbolAddress((void**)&degi, g_degi);
    cudaGetSymbolAddress((void**)&dis, g_dis);
    cudaGetSymbolAddress((void**)&rowptr, g_rowptr);
    cudaGetSymbolAddress((void**)&cursor, g_cursor);
    cudaGetSymbolAddress((void**)&csr, g_csr);
    cudaGetSymbolAddress((void**)&bsums, g_blocksums);
    cudaGetSymbolAddress((void**)&A, g_bufA);
    cudaGetSymbolAddress((void**)&B, g_bufB);
    cudaGetSymbolAddress((void**)&C, g_bufC);

    const int GEMM_SMEM = 64 * WS_STRIDE * 4 + 128 * XS_STRIDE * 4;          // 53248
    const int SAGE_SMEM = 128 * WS_STRIDE * 4 + 2 * 128 * XS_STRIDE * 4;     // 106496
    cudaFuncSetAttribute(gemm_tc_kernel<false, false>, cudaFuncAttributeMaxDynamicSharedMemorySize, GEMM_SMEM);
    cudaFuncSetAttribute(gemm_tc_kernel<true, true>,   cudaFuncAttributeMaxDynamicSharedMemorySize, GEMM_SMEM);
    cudaFuncSetAttribute(sage_tc_kernel<true>,  cudaFuncAttributeMaxDynamicSharedMemorySize, SAGE_SMEM);
    cudaFuncSetAttribute(sage_tc_kernel<false>, cudaFuncAttributeMaxDynamicSharedMemorySize, SAGE_SMEM);

    // one-time resource init (outside capture: the correctness run happens first)
    static cudaStream_t s2 = nullptr;
    static cudaEvent_t evFork = nullptr, evJoin = nullptr;
    if (!s2) {
        cudaStreamCreateWithFlags(&s2, cudaStreamNonBlocking);
        cudaEventCreateWithFlags(&evFork, cudaEventDisableTiming);
        cudaEventCreateWithFlags(&evJoin, cudaEventDisableTiming);
    }

    const int GEMM_GRID = (n + 127) / 128;
    const int GATH_GRID = (n + 15) / 16;
    const int NB = (n + 511) / 512;

    // ---- fork: CSR build on s2, concurrent with gemm1 on main ----
    cudaEventRecord(evFork, 0);
    cudaStreamWaitEvent(s2, evFork, 0);

    cudaMemsetAsync(degi, 0, n * sizeof(int), s2);
    deg_count_kernel<<<(E + 255) / 256, 256, 0, s2>>>(dst, E, degi);
    scan1_kernel<<<NB, 512, 0, s2>>>(degi, rowptr, bsums, dis, n);
    scan2_kernel<<<1, 512, 0, s2>>>(bsums, NB);
    scan3_kernel<<<(n + 512) / 512, 512, 0, s2>>>(rowptr, bsums, cursor, n, E);
    fill_csr_kernel<<<(E + 255) / 256, 256, 0, s2>>>(src, dst, cursor, csr, E);
    cudaEventRecord(evJoin, s2);

    // ---- layer 0 matmul (independent of CSR) ----
    gemm_tc_kernel<false, false><<<GEMM_GRID, 256, GEMM_SMEM>>>(x, gcn1_w, nullptr, A, n);

    cudaStreamWaitEvent(0, evJoin, 0);  // join before first gather

    // ---- layer 0: GCN1 + relu ----
    gather_kernel<true, true><<<GATH_GRID, 256>>>(rowptr, csr, A, dis, gcn1_b, C, n);

    // ---- layer 1: SAGE1 + residual + relu ----
    gather_kernel<false, false><<<GATH_GRID, 256>>>(rowptr, csr, C, dis, nullptr, B, n);
    sage_tc_kernel<true><<<GEMM_GRID, 256, SAGE_SMEM>>>(B, C, s1lw, s1lb, s1rw, A, n);

    // ---- layer 2: SAGE2 + residual ----
    gather_kernel<false, false><<<GATH_GRID, 256>>>(rowptr, csr, A, dis, nullptr, B, n);
    sage_tc_kernel<false><<<GEMM_GRID, 256, SAGE_SMEM>>>(B, A, s2lw, s2lb, s2rw, C, n);

    // ---- lin + relu ----
    gemm_tc_kernel<true, true><<<GEMM_GRID, 256, GEMM_SMEM>>>(C, linw, linb, A, n);

    // ---- layer 3: GCN2 ----
    gemm_tc_kernel<false, false><<<GEMM_GRID, 256, GEMM_SMEM>>>(A, gcn2_w, nullptr, C, n);
    gather_kernel<true, false><<<GATH_GRID, 256>>>(rowptr, csr, C, dis, gcn2_b, (float*)d_out, n);
}